// round 12
// baseline (speedup 1.0000x reference)
#include <cuda_runtime.h>

// ---------------------------------------------------------------------------
// LieSpline: SE(3) cubic B-spline interpolation.  B=32, N=2048, K=32.  FUSED.
//
// Block = 8 warps = 32 consecutive segments of one batch (grid 64 x 32).
// Phase 1: the 34 delta records the block needs are computed by threads
//   spread across ALL 8 warps (record r -> thread 8r; records 32,33 ->
//   threads 1,9), so every warp runs the record chain concurrently and the
//   __syncthreads barrier has ~zero skew.  Record layout (5 float4):
//     r0 = (tau.xyz | nd)
//     r1 = (U.xyz   | C1'.x)      C1' = (2/nd^2) * cross(phi,tau)
//     r2 = (C1'.y, C1'.z, C2'.x, C2'.y)  C2' = (1/nd^3)*cross(phi,cross(phi,tau))
//     r3 = (C2'.z, pose_t.xyz)
//     r4 = pose_q
//   Records with j > N are zero-filled (zero record => identity transform).
// Phase 2: warp w handles segments s_base+4w .. +3, lane = time sample.
//   4 interleaved compose chains, record-serial smem consumption, coalesced
//   float4 output via shared staging.
// ---------------------------------------------------------------------------

#define LS_B 32
#define LS_N 2048
#define LS_S (LS_N - 1)      // 2047 segments
#define SEG_PER_BLK 32
#define BLK_PER_B 64         // 64 * 32 = 2048 >= 2047
#define NRECB 34             // records s_base .. s_base+33

__device__ __forceinline__ float3 f3(float x, float y, float z) {
    return make_float3(x, y, z);
}
__device__ __forceinline__ float3 cross3(const float3 a, const float3 b) {
    return make_float3(a.y * b.z - a.z * b.y,
                       a.z * b.x - a.x * b.z,
                       a.x * b.y - a.y * b.x);
}
__device__ __forceinline__ float dot3(const float3 a, const float3 b) {
    return a.x * b.x + a.y * b.y + a.z * b.z;
}
__device__ __forceinline__ float3 qrot(const float4 q, const float3 v) {
    float3 qv = f3(q.x, q.y, q.z);
    float3 t = cross3(qv, v);
    t.x *= 2.0f; t.y *= 2.0f; t.z *= 2.0f;
    float3 c = cross3(qv, t);
    return f3(v.x + q.w * t.x + c.x,
              v.y + q.w * t.y + c.y,
              v.z + q.w * t.z + c.z);
}
__device__ __forceinline__ float4 qmul(const float4 a, const float4 b) {
    return make_float4(
        a.w * b.x + a.x * b.w + a.y * b.z - a.z * b.y,
        a.w * b.y + a.y * b.w + a.z * b.x - a.x * b.z,
        a.w * b.z + a.z * b.w + a.x * b.y - a.y * b.x,
        a.w * b.w - a.x * b.x - a.y * b.y - a.z * b.z);
}

struct Xf { float3 t; float4 q; };

// exp + in-place right-compose: T <- T * exp(wk * delta)
// record fields: r0 = tau|nd, r1 = U|C1'x, r2 = C1'yz C2'xy, c2z = C2'z
__device__ __forceinline__ void stepc(Xf& T,
                                      const float4 r0, const float4 r1,
                                      const float4 r2, float c2z,
                                      float wk) {
    float theta = wk * r0.w;
    float sh, ch;
    __sincosf(0.5f * theta, &sh, &ch);
    float alpha = sh * sh;                        // (1 - cos th) with K2 premult
    float beta  = fmaf(-(sh + sh), ch, theta);    // th - sin th  with rn3 premult
    float3 At;
    At.x = fmaf(beta, r2.z, fmaf(alpha, r1.w, wk * r0.x));
    At.y = fmaf(beta, r2.w, fmaf(alpha, r2.x, wk * r0.y));
    At.z = fmaf(beta, c2z,  fmaf(alpha, r2.y, wk * r0.z));
    float4 Aq = make_float4(sh * r1.x, sh * r1.y, sh * r1.z, ch);
    float3 r = qrot(T.q, At);
    T.t.x += r.x; T.t.y += r.y; T.t.z += r.z;
    T.q = qmul(T.q, Aq);
}

// ---------------------------------------------------------------------------
__global__ void __launch_bounds__(256, 4)
k_fused(const float* __restrict__ poses,
        const float* __restrict__ timev,
        float* __restrict__ out) {
    __shared__ __align__(16) float4 rec[NRECB * 5];     // 2720 B
    __shared__ __align__(16) float  stg[8 * 896];       // 28672 B

    const unsigned b      = blockIdx.y;
    const unsigned s_base = blockIdx.x * SEG_PER_BLK;
    const unsigned tid    = threadIdx.x;
    const float* pbase = poses + b * (LS_N * 7);

    // ------- Phase 1: 34 delta records, spread over ALL 8 warps -------------
    // record r -> thread 8r (r=0..31: lanes 0,8,16,24 of each warp);
    // records 32,33 -> threads 1,9 (extra lanes of warp 0).
    unsigned r = 0xFFFFFFFFu;
    if ((tid & 7u) == 0u)      r = tid >> 3;
    else if (tid == 1u)        r = 32u;
    else if (tid == 9u)        r = 33u;

    if (r != 0xFFFFFFFFu) {
        float4* o = rec + r * 5;
        unsigned j = s_base + r;             // delta index
        if (j > LS_N) {
            float4 z = make_float4(0.f, 0.f, 0.f, 0.f);
            o[0] = z; o[1] = z; o[2] = z; o[3] = z; o[4] = z;
        } else {
            unsigned pj = j > 0 ? j - 1 : 0;
            const float* pr = pbase + pj * 7;
            float3 t0 = f3(pr[0], pr[1], pr[2]);
            float4 q0 = make_float4(pr[3], pr[4], pr[5], pr[6]);
            o[4] = q0;
            if (j == 0 || j == LS_N) {
                float4 z = make_float4(0.f, 0.f, 0.f, 0.f);
                o[0] = z; o[1] = z; o[2] = z;
                o[3] = make_float4(0.f, t0.x, t0.y, t0.z);
            } else {
                const float* pr1 = pr + 7;
                float3 t1 = f3(pr1[0], pr1[1], pr1[2]);
                float4 q1 = make_float4(pr1[3], pr1[4], pr1[5], pr1[6]);

                float4 qi = make_float4(-q0.x, -q0.y, -q0.z, q0.w);
                float3 dt = f3(t1.x - t0.x, t1.y - t0.y, t1.z - t0.z);
                float3 t  = qrot(qi, dt);
                float4 q  = qmul(qi, q1);

                // so3_log
                float n2 = q.x * q.x + q.y * q.y + q.z * q.z;
                bool small = n2 < 1e-12f;
                float ns = small ? 1.0f : n2;
                float rn = rsqrtf(ns);
                float n  = ns * rn;
                float factor;
                if (small) {
                    float iw = __fdividef(1.0f, q.w);
                    factor = 2.0f * iw - (2.0f / 3.0f) * n2 * iw * iw * iw;
                } else {
                    factor = 2.0f * atan2f(n, q.w) * rn;
                }
                float3 phi = f3(factor * q.x, factor * q.y, factor * q.z);

                // jl_inv
                float t2 = dot3(phi, phi);
                bool sm2 = t2 < 1e-12f;
                float t2s = sm2 ? 1.0f : t2;
                float rth = rsqrtf(t2s);
                float theta = t2s * rth;
                float s, cth;
                __sincosf(theta, &s, &cth);
                float s_safe = (fabsf(s) < 1e-6f) ? 1e-6f : s;
                float c;
                if (sm2) {
                    c = (1.0f / 12.0f) + t2 * (1.0f / 720.0f);
                } else {
                    c = rth * rth - __fdividef(1.0f + cth, 2.0f * theta * s_safe);
                }
                float3 x1 = cross3(phi, t);
                float3 x2 = cross3(phi, x1);
                float3 tau = f3(t.x - 0.5f * x1.x + c * x2.x,
                                t.y - 0.5f * x1.y + c * x2.y,
                                t.z - 0.5f * x1.z + c * x2.z);

                float nd2 = dot3(phi, phi);
                if (nd2 < 1e-24f) {
                    o[0] = make_float4(tau.x, tau.y, tau.z, 0.f);
                    o[1] = make_float4(0.f, 0.f, 0.f, 0.f);
                    o[2] = make_float4(0.f, 0.f, 0.f, 0.f);
                    o[3] = make_float4(0.f, t0.x, t0.y, t0.z);
                } else {
                    float rnd = rsqrtf(nd2);
                    float nd  = nd2 * rnd;
                    float K2  = 2.0f * rnd * rnd;
                    float rn3 = rnd * rnd * rnd;
                    float3 U  = f3(phi.x * rnd, phi.y * rnd, phi.z * rnd);
                    float3 C1 = cross3(phi, tau);
                    float3 C2 = cross3(phi, C1);
                    C1.x *= K2;  C1.y *= K2;  C1.z *= K2;
                    C2.x *= rn3; C2.y *= rn3; C2.z *= rn3;
                    o[0] = make_float4(tau.x, tau.y, tau.z, nd);
                    o[1] = make_float4(U.x, U.y, U.z, C1.x);
                    o[2] = make_float4(C1.y, C1.z, C2.x, C2.y);
                    o[3] = make_float4(C2.z, t0.x, t0.y, t0.z);
                }
            }
        }
    }

    // per-lane weights (independent of phase 1 -> before the barrier)
    const unsigned w    = tid >> 5;
    const unsigned lane = tid & 31;
    float u  = __ldg(timev + lane);
    float u2 = u * u;
    float u3 = u2 * u;
    const float w0 = (5.0f + 3.0f * u - 3.0f * u2 + u3) * (1.0f / 6.0f);
    const float w1 = (1.0f + 3.0f * u + 3.0f * u2 - 2.0f * u3) * (1.0f / 6.0f);
    const float w2 = u3 * (1.0f / 6.0f);

    __syncthreads();

    // ---------------- Phase 2: 4 interleaved compose chains -----------------
    const unsigned s0 = s_base + 4 * w;
    unsigned nvalid = LS_S - s0;          // >= 1 always (s0 <= 2044)
    if (nvalid > 4) nvalid = 4;

    const float4* R = rec + (4 * w) * 5;  // warp-uniform smem

    Xf T0, T1, T2, T3;
    {
        float4 r0 = R[0], r1 = R[1], r2 = R[2], r3 = R[3], r4 = R[4];
        T0.t = f3(r3.y, r3.z, r3.w);  T0.q = r4;
        stepc(T0, r0, r1, r2, r3.x, w0);
    }
    {
        const float4* Rr = R + 5;
        float4 r0 = Rr[0], r1 = Rr[1], r2 = Rr[2], r3 = Rr[3], r4 = Rr[4];
        T1.t = f3(r3.y, r3.z, r3.w);  T1.q = r4;
        stepc(T1, r0, r1, r2, r3.x, w0);
        stepc(T0, r0, r1, r2, r3.x, w1);
    }
    {
        const float4* Rr = R + 10;
        float4 r0 = Rr[0], r1 = Rr[1], r2 = Rr[2], r3 = Rr[3], r4 = Rr[4];
        T2.t = f3(r3.y, r3.z, r3.w);  T2.q = r4;
        stepc(T2, r0, r1, r2, r3.x, w0);
        stepc(T1, r0, r1, r2, r3.x, w1);
        stepc(T0, r0, r1, r2, r3.x, w2);
    }
    {
        const float4* Rr = R + 15;
        float4 r0 = Rr[0], r1 = Rr[1], r2 = Rr[2], r3 = Rr[3], r4 = Rr[4];
        T3.t = f3(r3.y, r3.z, r3.w);  T3.q = r4;
        stepc(T3, r0, r1, r2, r3.x, w0);
        stepc(T2, r0, r1, r2, r3.x, w1);
        stepc(T1, r0, r1, r2, r3.x, w2);
    }
    {
        const float4* Rr = R + 20;
        float4 r0 = Rr[0], r1 = Rr[1], r2 = Rr[2];
        float c2z = Rr[3].x;
        stepc(T3, r0, r1, r2, c2z, w1);
        stepc(T2, r0, r1, r2, c2z, w2);
    }
    {
        const float4* Rr = R + 25;
        float4 r0 = Rr[0], r1 = Rr[1], r2 = Rr[2];
        float c2z = Rr[3].x;
        stepc(T3, r0, r1, r2, c2z, w2);
    }

    // stage through shared; 896 contiguous floats per warp
    float* smw = stg + w * 896;
    unsigned o7 = lane * 7;
    {
        float* p = smw + o7;
        p[0] = T0.t.x; p[1] = T0.t.y; p[2] = T0.t.z;
        p[3] = T0.q.x; p[4] = T0.q.y; p[5] = T0.q.z; p[6] = T0.q.w;
        p += 224;
        p[0] = T1.t.x; p[1] = T1.t.y; p[2] = T1.t.z;
        p[3] = T1.q.x; p[4] = T1.q.y; p[5] = T1.q.z; p[6] = T1.q.w;
        p += 224;
        p[0] = T2.t.x; p[1] = T2.t.y; p[2] = T2.t.z;
        p[3] = T2.q.x; p[4] = T2.q.y; p[5] = T2.q.z; p[6] = T2.q.w;
        p += 224;
        p[0] = T3.t.x; p[1] = T3.t.y; p[2] = T3.t.z;
        p[3] = T3.q.x; p[4] = T3.q.y; p[5] = T3.q.z; p[6] = T3.q.w;
    }
    __syncwarp();

    const float4* sm4 = (const float4*)smw;
    unsigned pair0 = b * LS_S + s0;
    float4* ob4 = (float4*)(out) + pair0 * 56;   // 224 floats = 56 float4
    unsigned nf4 = nvalid * 56;                  // 224 (full) or 168 (tail)
#pragma unroll 7
    for (unsigned i = lane; i < nf4; i += 32)
        ob4[i] = sm4[i];
}

extern "C" void kernel_launch(void* const* d_in, const int* in_sizes, int n_in,
                              void* d_out, int out_size) {
    (void)n_in; (void)out_size;
    const float* poses = (const float*)d_in[0];
    const float* timev = (const float*)d_in[1];
    float* out = (float*)d_out;

    dim3 grid(BLK_PER_B, LS_B);
    k_fused<<<grid, 256>>>(poses, timev, out);
}

// round 13
// speedup vs baseline: 1.0844x; 1.0844x over previous
#include <cuda_runtime.h>

// ---------------------------------------------------------------------------
// LieSpline: SE(3) cubic B-spline.  B=32, N=2048, K=32.
//
// Kernel 1 (R9): per padded delta j: se3_log + exp precomputes + pose,
//   5 float4 per record in g_pre:
//     r0=(tau|nd) r1=(U|C1'x) r2=(C1'y,C1'z,C2'x,C2'y) r3=(C2'z,pose_t) r4=pose_q
// Kernel 2 (NEW, packed f32x2 over SAMPLE pairs):
//   warp = 2 consecutive segments.  Lanes 0-15 -> segment s0, lanes 16-31 ->
//   segment s0+1; each lane evaluates TWO time samples (k, k+16) packed in
//   f32x2 registers.  Records are stored in smem PRE-DUPLICATED (each scalar
//   as (x,x) u64) by the cooperative loader, so every packed operand is a
//   single LDS.64 — no pack movs in the hot path.  All FMA/MUL/ADD become
//   fma.rn.f32x2 (FFMA2): half the fma-pipe instructions, which is the
//   measured bottleneck (~21us FFMA roof in the scalar versions).
// ---------------------------------------------------------------------------

#define LS_B 32
#define LS_N 2048
#define LS_J (LS_N + 1)   // 2049 deltas per batch
#define REC 5             // float4s per record in g_pre
#define LS_S (LS_N - 1)   // 2047 segments
#define LS_M 1024         // segment-pairs per batch

__device__ float4 g_pre[LS_B * LS_J * REC];   // 5.2 MB scratch

typedef unsigned long long u64;

__device__ __forceinline__ float3 f3(float x, float y, float z) {
    return make_float3(x, y, z);
}
__device__ __forceinline__ float3 cross3(const float3 a, const float3 b) {
    return make_float3(a.y * b.z - a.z * b.y,
                       a.z * b.x - a.x * b.z,
                       a.x * b.y - a.y * b.x);
}
__device__ __forceinline__ float dot3(const float3 a, const float3 b) {
    return a.x * b.x + a.y * b.y + a.z * b.z;
}
__device__ __forceinline__ float3 qrot(const float4 q, const float3 v) {
    float3 qv = f3(q.x, q.y, q.z);
    float3 t = cross3(qv, v);
    t.x *= 2.0f; t.y *= 2.0f; t.z *= 2.0f;
    float3 c = cross3(qv, t);
    return f3(v.x + q.w * t.x + c.x,
              v.y + q.w * t.y + c.y,
              v.z + q.w * t.z + c.z);
}
__device__ __forceinline__ float4 qmul(const float4 a, const float4 b) {
    return make_float4(
        a.w * b.x + a.x * b.w + a.y * b.z - a.z * b.y,
        a.w * b.y + a.y * b.w + a.z * b.x - a.x * b.z,
        a.w * b.z + a.z * b.w + a.x * b.y - a.y * b.x,
        a.w * b.w - a.x * b.x - a.y * b.y - a.z * b.z);
}

// ---------------- packed f32x2 helpers ----------------
__device__ __forceinline__ u64 pk2(float lo, float hi) {
    u64 r; asm("mov.b64 %0, {%1, %2};" : "=l"(r) : "f"(lo), "f"(hi)); return r;
}
__device__ __forceinline__ void unpk2(u64 v, float& lo, float& hi) {
    asm("mov.b64 {%0, %1}, %2;" : "=f"(lo), "=f"(hi) : "l"(v));
}
__device__ __forceinline__ u64 f2mul(u64 a, u64 b) {
    u64 r; asm("mul.rn.f32x2 %0, %1, %2;" : "=l"(r) : "l"(a), "l"(b)); return r;
}
__device__ __forceinline__ u64 f2add(u64 a, u64 b) {
    u64 r; asm("add.rn.f32x2 %0, %1, %2;" : "=l"(r) : "l"(a), "l"(b)); return r;
}
__device__ __forceinline__ u64 f2fma(u64 a, u64 b, u64 c) {
    u64 r; asm("fma.rn.f32x2 %0, %1, %2, %3;" : "=l"(r) : "l"(a), "l"(b), "l"(c)); return r;
}
__device__ __forceinline__ u64 f2neg(u64 a) { return a ^ 0x8000000080000000ULL; }

// ---------------------------------------------------------------------------
// Kernel 1: per-(b, j) relative-pose log + precompute (R9, unchanged)
// ---------------------------------------------------------------------------
__global__ void __launch_bounds__(128) k_delta(const float* __restrict__ poses) {
    unsigned idx = blockIdx.x * blockDim.x + threadIdx.x;
    if (idx >= LS_B * LS_J) return;
    unsigned b = idx / LS_J;
    unsigned j = idx - b * LS_J;
    float4* o = g_pre + idx * REC;
    const float* pbase = poses + b * (LS_N * 7);

    unsigned pj = j > 0 ? j - 1 : 0;
    const float* pr = pbase + pj * 7;
    float3 t0 = f3(pr[0], pr[1], pr[2]);
    float4 q0 = make_float4(pr[3], pr[4], pr[5], pr[6]);
    o[4] = q0;

    if (j == 0 || j == LS_N) {
        float4 z = make_float4(0.f, 0.f, 0.f, 0.f);
        o[0] = z; o[1] = z; o[2] = z;
        o[3] = make_float4(0.f, t0.x, t0.y, t0.z);
        return;
    }
    const float* pr1 = pr + 7;
    float3 t1 = f3(pr1[0], pr1[1], pr1[2]);
    float4 q1 = make_float4(pr1[3], pr1[4], pr1[5], pr1[6]);

    float4 qi = make_float4(-q0.x, -q0.y, -q0.z, q0.w);
    float3 dt = f3(t1.x - t0.x, t1.y - t0.y, t1.z - t0.z);
    float3 t  = qrot(qi, dt);
    float4 q  = qmul(qi, q1);

    float n2 = q.x * q.x + q.y * q.y + q.z * q.z;
    bool small = n2 < 1e-12f;
    float ns = small ? 1.0f : n2;
    float rn = rsqrtf(ns);
    float n  = ns * rn;
    float factor;
    if (small) {
        float iw = __fdividef(1.0f, q.w);
        factor = 2.0f * iw - (2.0f / 3.0f) * n2 * iw * iw * iw;
    } else {
        factor = 2.0f * atan2f(n, q.w) * rn;
    }
    float3 phi = f3(factor * q.x, factor * q.y, factor * q.z);

    float t2 = dot3(phi, phi);
    bool sm2 = t2 < 1e-12f;
    float t2s = sm2 ? 1.0f : t2;
    float rth = rsqrtf(t2s);
    float theta = t2s * rth;
    float s, cth;
    __sincosf(theta, &s, &cth);
    float s_safe = (fabsf(s) < 1e-6f) ? 1e-6f : s;
    float c;
    if (sm2) {
        c = (1.0f / 12.0f) + t2 * (1.0f / 720.0f);
    } else {
        c = rth * rth - __fdividef(1.0f + cth, 2.0f * theta * s_safe);
    }
    float3 x1 = cross3(phi, t);
    float3 x2 = cross3(phi, x1);
    float3 tau = f3(t.x - 0.5f * x1.x + c * x2.x,
                    t.y - 0.5f * x1.y + c * x2.y,
                    t.z - 0.5f * x1.z + c * x2.z);

    float nd2 = dot3(phi, phi);
    if (nd2 < 1e-24f) {
        o[0] = make_float4(tau.x, tau.y, tau.z, 0.f);
        o[1] = make_float4(0.f, 0.f, 0.f, 0.f);
        o[2] = make_float4(0.f, 0.f, 0.f, 0.f);
        o[3] = make_float4(0.f, t0.x, t0.y, t0.z);
        return;
    }
    float rnd = rsqrtf(nd2);
    float nd  = nd2 * rnd;
    float K2  = 2.0f * rnd * rnd;
    float rn3 = rnd * rnd * rnd;
    float3 U  = f3(phi.x * rnd, phi.y * rnd, phi.z * rnd);
    float3 C1 = cross3(phi, tau);
    float3 C2 = cross3(phi, C1);
    C1.x *= K2;  C1.y *= K2;  C1.z *= K2;
    C2.x *= rn3; C2.y *= rn3; C2.z *= rn3;
    o[0] = make_float4(tau.x, tau.y, tau.z, nd);
    o[1] = make_float4(U.x, U.y, U.z, C1.x);
    o[2] = make_float4(C1.y, C1.z, C2.x, C2.y);
    o[3] = make_float4(C2.z, t0.x, t0.y, t0.z);
}

// ---------------------------------------------------------------------------
// Packed transform (two samples per thread)
// ---------------------------------------------------------------------------
struct X2 { u64 tx, ty, tz, qx, qy, qz, qw; };

// Duplicated-record scalar indices (u64 slots), matching g_pre scalar order:
//  0:tau.x 1:tau.y 2:tau.z 3:nd   4:U.x 5:U.y 6:U.z 7:C1x
//  8:C1y 9:C1z 10:C2x 11:C2y    12:C2z 13:pt.x 14:pt.y 15:pt.z
// 16:q.x 17:q.y 18:q.z 19:q.w
__device__ __forceinline__ void stepp(X2& T, const u64* __restrict__ D, u64 W) {
    u64 th = f2mul(W, D[3]);                 // theta (both samples)
    float tha, thb;
    unpk2(th, tha, thb);
    float sa, ca, sb, cb;
    __sincosf(0.5f * tha, &sa, &ca);
    __sincosf(0.5f * thb, &sb, &cb);
    u64 sh = pk2(sa, sb), ch = pk2(ca, cb);
    u64 alpha = f2mul(sh, sh);                           // (1-cos)/2, K2 premult
    u64 beta  = f2fma(f2neg(f2add(sh, sh)), ch, th);     // th - sin th, rn3 premult
    u64 Atx = f2fma(beta, D[10], f2fma(alpha, D[7], f2mul(W, D[0])));
    u64 Aty = f2fma(beta, D[11], f2fma(alpha, D[8], f2mul(W, D[1])));
    u64 Atz = f2fma(beta, D[12], f2fma(alpha, D[9], f2mul(W, D[2])));
    u64 Aqx = f2mul(sh, D[4]);
    u64 Aqy = f2mul(sh, D[5]);
    u64 Aqz = f2mul(sh, D[6]);
    u64 Aqw = ch;

    // T = T * A
    u64 nx = f2neg(T.qx), ny = f2neg(T.qy), nz = f2neg(T.qz);
    // c = 2 * cross(T.qv, At)
    u64 cx = f2fma(T.qy, Atz, f2mul(nz, Aty));
    u64 cy = f2fma(T.qz, Atx, f2mul(nx, Atz));
    u64 cz = f2fma(T.qx, Aty, f2mul(ny, Atx));
    cx = f2add(cx, cx); cy = f2add(cy, cy); cz = f2add(cz, cz);
    // d = cross(T.qv, c)
    u64 dx = f2fma(T.qy, cz, f2mul(nz, cy));
    u64 dy = f2fma(T.qz, cx, f2mul(nx, cz));
    u64 dz = f2fma(T.qx, cy, f2mul(ny, cx));
    T.tx = f2add(T.tx, f2add(Atx, f2fma(T.qw, cx, dx)));
    T.ty = f2add(T.ty, f2add(Aty, f2fma(T.qw, cy, dy)));
    T.tz = f2add(T.tz, f2add(Atz, f2fma(T.qw, cz, dz)));
    u64 rqx = f2fma(T.qw, Aqx, f2fma(T.qx, Aqw, f2fma(T.qy, Aqz, f2mul(nz, Aqy))));
    u64 rqy = f2fma(T.qw, Aqy, f2fma(T.qy, Aqw, f2fma(T.qz, Aqx, f2mul(nx, Aqz))));
    u64 rqz = f2fma(T.qw, Aqz, f2fma(T.qz, Aqw, f2fma(T.qx, Aqy, f2mul(ny, Aqx))));
    u64 rqw = f2fma(T.qw, Aqw, f2fma(nx, Aqx, f2fma(ny, Aqy, f2mul(nz, Aqz))));
    T.qx = rqx; T.qy = rqy; T.qz = rqz; T.qw = rqw;
}

// ---------------------------------------------------------------------------
// Kernel 2: warp = 2 segments; lanes 0-15 seg s0, lanes 16-31 seg s0+1;
// each lane evaluates samples (k, k+16) packed.
// ---------------------------------------------------------------------------
__global__ void __launch_bounds__(256) k_spline(const float* __restrict__ timev,
                                                float* __restrict__ out) {
    __shared__ __align__(16) u64   recd[8 * 80];   // 4 records x 20 dup-scalars
    __shared__ __align__(16) float stg[8 * 448];

    unsigned w    = threadIdx.x >> 5;
    unsigned lane = threadIdx.x & 31;
    unsigned gp = blockIdx.x * 8 + w;
    if (gp >= LS_B * LS_M) return;
    unsigned b = gp >> 10;
    unsigned m = gp & (LS_M - 1);
    unsigned s0 = 2 * m;
    bool tail = (s0 + 1 >= LS_S);

    // ---- cooperative load of records s0..s0+3, duplicated per scalar ----
    u64* rd = recd + w * 80;
    {
        unsigned gbase = (b * LS_J + s0) * REC;
        const unsigned GMAX = LS_B * LS_J * REC - 1;
        unsigned gidx = gbase + lane;
        if (gidx > GMAX) gidx = GMAX;        // tail clamp (unused results)
        if (lane < 20) {
            float4 v = g_pre[gidx];
            u64* d = rd + lane * 4;
            d[0] = pk2(v.x, v.x);
            d[1] = pk2(v.y, v.y);
            d[2] = pk2(v.z, v.z);
            d[3] = pk2(v.w, v.w);
        }
    }
    __syncwarp();

    unsigned half = lane >> 4;     // 0: segment s0, 1: segment s0+1
    unsigned k    = lane & 15;     // sample pair (k, k+16)

    // packed spline weights for the two samples
    float ua = __ldg(timev + k);
    float ub = __ldg(timev + k + 16);
    float ua2 = ua * ua, ua3 = ua2 * ua;
    float ub2 = ub * ub, ub3 = ub2 * ub;
    u64 W0 = pk2((5.0f + 3.0f * ua - 3.0f * ua2 + ua3) * (1.0f / 6.0f),
                 (5.0f + 3.0f * ub - 3.0f * ub2 + ub3) * (1.0f / 6.0f));
    u64 W1 = pk2((1.0f + 3.0f * ua + 3.0f * ua2 - 2.0f * ua3) * (1.0f / 6.0f),
                 (1.0f + 3.0f * ub + 3.0f * ub2 - 2.0f * ub3) * (1.0f / 6.0f));
    u64 W2 = pk2(ua3 * (1.0f / 6.0f), ub3 * (1.0f / 6.0f));

    const u64* D = rd + half * 20;   // record s0+half (uniform per half-warp)

    // T = pose  (duplicated pose scalars load directly as packed)
    X2 T;
    T.tx = D[13]; T.ty = D[14]; T.tz = D[15];
    T.qx = D[16]; T.qy = D[17]; T.qz = D[18]; T.qw = D[19];

    stepp(T, D,      W0);
    stepp(T, D + 20, W1);
    stepp(T, D + 40, W2);

    // ---- staging: unpack both samples into the segment's 224-float block
    float* smw = stg + w * 448 + half * 224;
    {
        float va, vb;
        unsigned oA = k * 7, oB = oA + 112;   // (k+16)*7 = k*7 + 112
        unpk2(T.tx, va, vb); smw[oA + 0] = va; smw[oB + 0] = vb;
        unpk2(T.ty, va, vb); smw[oA + 1] = va; smw[oB + 1] = vb;
        unpk2(T.tz, va, vb); smw[oA + 2] = va; smw[oB + 2] = vb;
        unpk2(T.qx, va, vb); smw[oA + 3] = va; smw[oB + 3] = vb;
        unpk2(T.qy, va, vb); smw[oA + 4] = va; smw[oB + 4] = vb;
        unpk2(T.qz, va, vb); smw[oA + 5] = va; smw[oB + 5] = vb;
        unpk2(T.qw, va, vb); smw[oA + 6] = va; smw[oB + 6] = vb;
    }
    __syncwarp();

    // ---- coalesced store: 448 floats (2 segments) or 224 on tail
    const float4* sm4 = (const float4*)(stg + w * 448);
    unsigned pair0 = b * LS_S + s0;
    float4* ob4 = (float4*)(out) + pair0 * 56;
    if (!tail) {
        ob4[lane]      = sm4[lane];
        ob4[lane + 32] = sm4[lane + 32];
        ob4[lane + 64] = sm4[lane + 64];
        if (lane < 16) ob4[lane + 96] = sm4[lane + 96];
    } else {
        ob4[lane] = sm4[lane];
        if (lane < 24) ob4[lane + 32] = sm4[lane + 32];
    }
}

extern "C" void kernel_launch(void* const* d_in, const int* in_sizes, int n_in,
                              void* d_out, int out_size) {
    (void)n_in; (void)out_size;
    const float* poses = (const float*)d_in[0];
    const float* timev = (const float*)d_in[1];
    float* out = (float*)d_out;

    int tot1 = LS_B * LS_J;
    k_delta<<<(tot1 + 127) / 128, 128>>>(poses);

    int tot2 = LS_B * LS_M;   // 32768 warps
    k_spline<<<(tot2 + 7) / 8, 256>>>(timev, out);
}